// round 14
// baseline (speedup 1.0000x reference)
#include <cuda_runtime.h>
#include <cuda_fp16.h>
#include <math.h>
#include <stdint.h>

#define T_STEPS 32
#define NB      256
#define HID     64
#define G3      192      // 3*HID
#define SUB_OFF 128
#define ACT_OFF 146
#define IN_FEAT 147
#define STATE   78
#define GRU_IN  8384
#define CONV_COLS 8192
#define SUB_V   20
#define NSUB    6
#define SUBDIM  3

// ---------------- scratch (device globals; no allocations allowed) ----------
__device__ float   d_Wt[GRU_IN * G3];           // full w_ih transposed        6.4 MB
__device__ float   d_R[3 * SUB_V * G3];         // R[(j*20+v)*192+g]
__device__ float   d_Tab[128 * 16 * G3];        // Tab[(pos*16+v)*192+g]       1.6 MB
__device__ __half2 d_Tab2h[64 * 256 * 96];      // Tab2[pp][v1*16+v2][g/2]     6.3 MB
__device__ float   d_gxc[T_STEPS * NB * G3];    // conv-part of gx + b_ih      6.3 MB

// grid barrier state (generation-based; survives graph replays without reset)
__device__ unsigned int          g_cnt = 0;
__device__ volatile unsigned int g_gen = 0;

__device__ __forceinline__ float tanhf_fast(float x) {
    float y;
    asm("tanh.approx.f32 %0, %1;" : "=f"(y) : "f"(x));
    return y;
}
__device__ __forceinline__ float sigf(float x) {       // sigmoid via MUFU.TANH
    return fmaf(0.5f, tanhf_fast(0.5f * x), 0.5f);
}
__device__ __forceinline__ unsigned long long fma2(unsigned long long a,
                                                   unsigned long long b,
                                                   unsigned long long c) {
    unsigned long long d;
    asm("fma.rn.f32x2 %0, %1, %2, %3;" : "=l"(d) : "l"(a), "l"(b), "l"(c));
    return d;
}
__device__ __forceinline__ float2 unpk(unsigned long long v) {
    float2 r;
    asm("mov.b64 {%0,%1}, %2;" : "=f"(r.x), "=f"(r.y) : "l"(v));
    return r;
}

__device__ __forceinline__ void grid_sync(unsigned nb) {
    __syncthreads();
    if (threadIdx.x == 0) {
        unsigned target = g_gen + 1;
        __threadfence();
        unsigned old = atomicAdd(&g_cnt, 1u);
        if (old == nb - 1) {
            g_cnt = 0;
            __threadfence();
            g_gen = target;
        } else {
            while (g_gen < target) { __nanosleep(64); }
        }
        __threadfence();
    }
    __syncthreads();
}

// ---------------- K1: transpose ALL 8384 columns of w_ih --------------------
__global__ void __launch_bounds__(1024) k_prep(const float* __restrict__ w_ih) {
    __shared__ float tile[32][33];
    int cx = blockIdx.x % 262, cy = blockIdx.x / 262;
    int tx = threadIdx.x % 32, ty = threadIdx.x / 32;
    tile[ty][tx] = w_ih[(size_t)(cy * 32 + ty) * GRU_IN + cx * 32 + tx];
    __syncthreads();
    d_Wt[(size_t)(cx * 32 + ty) * G3 + cy * 32 + tx] = tile[tx][ty];
}

// ---------------- K2: Tab (blocks 0..127, E computed in-block) + R (128..187)
__global__ void __launch_bounds__(192) k_tabER(const float* __restrict__ conv_w,
                                               const float* __restrict__ obs_emb,
                                               const float* __restrict__ sub_emb,
                                               const float* __restrict__ conv_b) {
    if (blockIdx.x >= 128) {             // ---- R part ----
        __shared__ float se[64];
        int b = blockIdx.x - 128;        // 0..59
        int j = b / 20, v = b % 20;
        int g = threadIdx.x;
        if (g < 64) se[g] = sub_emb[v * HID + g];
        __syncthreads();
        float acc = 0.f;
        #pragma unroll 8
        for (int h = 0; h < 64; h++)
            acc += d_Wt[(size_t)(CONV_COLS + j * 64 + h) * G3 + g] * se[h];
        d_R[(size_t)(j * SUB_V + v) * G3 + g] = acc;
        return;
    }
    // ---- Tab part ----
    __shared__ float E_s[2048];
    __shared__ float cb_s[128];
    __shared__ float cw[128 * 65];
    __shared__ float oe[16 * 65];
    int pos = blockIdx.x;                // 0..127, pos = d*64 + s
    int d = pos >> 6, s = pos & 63;
    int g = threadIdx.x;

    for (int i = g; i < 128 * 64; i += 192) {
        int o = i >> 6, h = i & 63;
        cw[o * 65 + h] = conv_w[o * 128 + d * 64 + h];
    }
    for (int i = g; i < 1024; i += 192) {
        int v = i >> 6, h = i & 63;
        oe[v * 65 + h] = obs_emb[v * HID + h];
    }
    if (g < 128) cb_s[g] = conv_b[g];
    __syncthreads();

    for (int i = g; i < 2048; i += 192) {
        int o = i >> 4, v = i & 15;
        float a = 0.f;
        #pragma unroll 8
        for (int h = 0; h < 64; h++)
            a += cw[o * 65 + h] * oe[v * 65 + h];
        E_s[i] = a;
    }
    __syncthreads();

    float acc[16];
    #pragma unroll
    for (int v = 0; v < 16; v++) acc[v] = 0.f;
    float cacc = 0.f;
    for (int o = 0; o < 128; o += 8) {
        float w[8];
        #pragma unroll
        for (int k = 0; k < 8; k++)
            w[k] = d_Wt[(size_t)((o + k) * 64 + s) * G3 + g];
        #pragma unroll
        for (int k = 0; k < 8; k++) {
            cacc += w[k] * cb_s[o + k];
            #pragma unroll
            for (int v = 0; v < 16; v++) acc[v] += w[k] * E_s[(o + k) * 16 + v];
        }
    }
    if (d != 0) cacc = 0.f;
    #pragma unroll
    for (int v = 0; v < 16; v++)
        d_Tab[(size_t)(pos * 16 + v) * G3 + g] = acc[v] + cacc;
}

// ---------------- K3: fused tab2h (phase 1) + gxc (phase 2), grid 1024 ------
__global__ void __launch_bounds__(192, 7) k_tabgx(const float* __restrict__ inputs,
                                                  const float* __restrict__ b_ih) {
    {
        int blk = blockIdx.x;            // 0..1023
        int pp = blk >> 4, v1 = blk & 15;
        int lane = threadIdx.x % 48;
        int vg   = threadIdx.x / 48;
        float4 t1 = reinterpret_cast<const float4*>(
            &d_Tab[(size_t)((2 * pp) * 16 + v1) * G3])[lane];
        float4 t2r[4];
        #pragma unroll
        for (int k = 0; k < 4; k++) {
            int v2 = vg * 4 + k;
            t2r[k] = reinterpret_cast<const float4*>(
                &d_Tab[(size_t)((2 * pp + 1) * 16 + v2) * G3])[lane];
        }
        uint2* outb = reinterpret_cast<uint2*>(d_Tab2h + (size_t)(pp * 256 + v1 * 16) * 96);
        #pragma unroll
        for (int k = 0; k < 4; k++) {
            int v2 = vg * 4 + k;
            __half2 h0 = __floats2half2_rn(t1.x + t2r[k].x, t1.y + t2r[k].y);
            __half2 h1 = __floats2half2_rn(t1.z + t2r[k].z, t1.w + t2r[k].w);
            uint2 u;
            u.x = *reinterpret_cast<uint32_t*>(&h0);
            u.y = *reinterpret_cast<uint32_t*>(&h1);
            outb[(size_t)v2 * 48 + lane] = u;
        }
    }

    grid_sync(gridDim.x);

    {
        __shared__ int pv[8][64];
        int base_tn = blockIdx.x * 8;
        for (int i = threadIdx.x; i < 512; i += 192) {
            int s = i >> 6, pp = i & 63;
            const float* row = inputs + (size_t)(base_tn + s) * IN_FEAT;
            pv[s][pp] = __float2int_rn(row[2 * pp]) * 16 + __float2int_rn(row[2 * pp + 1]);
        }
        __syncthreads();
        int s = threadIdx.x / 24;
        int q = threadIdx.x % 24;
        const uint4* tab = reinterpret_cast<const uint4*>(d_Tab2h);
        float4 b0 = reinterpret_cast<const float4*>(b_ih)[q * 2];
        float4 b1 = reinterpret_cast<const float4*>(b_ih)[q * 2 + 1];
        float a0 = b0.x, a1 = b0.y, a2 = b0.z, a3 = b0.w;
        float a4 = b1.x, a5 = b1.y, a6 = b1.z, a7 = b1.w;
        const int* pvr = pv[s];
        #pragma unroll 8
        for (int pp = 0; pp < 64; pp++) {
            uint4 u = tab[(size_t)((pp << 8) + pvr[pp]) * 24 + q];
            const __half2* h = reinterpret_cast<const __half2*>(&u);
            float2 f0 = __half22float2(h[0]);
            float2 f1 = __half22float2(h[1]);
            float2 f2 = __half22float2(h[2]);
            float2 f3 = __half22float2(h[3]);
            a0 += f0.x; a1 += f0.y; a2 += f1.x; a3 += f1.y;
            a4 += f2.x; a5 += f2.y; a6 += f3.x; a7 += f3.y;
        }
        float4* outp = reinterpret_cast<float4*>(d_gxc) + (size_t)(base_tn + s) * 48 + q * 2;
        outp[0] = make_float4(a0, a1, a2, a3);
        outp[1] = make_float4(a4, a5, a6, a7);
    }
}

// ---------------- K4: recurrence, 2 samples x 192 rows x 2 halves = 768 thr -
#define BAR_TS() asm volatile("bar.sync %0, %1;" :: "r"(ts + 1), "r"(384) : "memory")

__global__ void __launch_bounds__(768) k_rec(
    const float* __restrict__ inputs, const float* __restrict__ hx,
    const float* __restrict__ w_hh, const float* __restrict__ b_hh,
    const float* __restrict__ critic_w, const float* __restrict__ critic_b,
    const float* __restrict__ phi_w, const float* __restrict__ phi_b,
    float* __restrict__ out)
{
    __shared__ float Q_s[2][NSUB][G3];
    __shared__ float A[2][G3], B[2][G3];
    __shared__ __align__(16) float h_s[2][HID];
    __shared__ float phi_s[HID], crit_s[HID], bhh_s[G3];
    __shared__ float red[2][4];
    __shared__ int flag[2];

    int ts   = threadIdx.x / 384;        // sample slot 0/1
    int u    = threadIdx.x % 384;        // 0..383
    int g    = u >> 1;                   // gate row 0..191
    int half = u & 1;                    // h-half 0/1 (adjacent lanes)
    int n    = blockIdx.x * 2 + ts;

    // half a w row, packed f32x2 (32 floats = 16 u64)
    unsigned long long wreg2[16];
    {
        const ulonglong2* wg = reinterpret_cast<const ulonglong2*>(
            w_hh + (size_t)g * HID + half * 32);
        #pragma unroll
        for (int k = 0; k < 8; k++) {
            ulonglong2 t = wg[k];
            wreg2[2 * k] = t.x; wreg2[2 * k + 1] = t.y;
        }
    }

    if (ts == 0) {
        if (u < G3) bhh_s[u] = b_hh[u];
        if (u < HID) { phi_s[u] = phi_w[u]; crit_s[u] = critic_w[u]; }
    }

    // Q_s: each (g,half) thread builds 3 of the 6 entries
    const float* in0 = inputs + (size_t)n * IN_FEAT;
    #pragma unroll
    for (int s = 0; s < 3; s++) {
        int ss = half * 3 + s;
        float q = 0.f;
        #pragma unroll
        for (int j = 0; j < SUBDIM; j++) {
            int v = __float2int_rn(in0[SUB_OFF + ss * SUBDIM + j]);
            q += d_R[(size_t)(j * SUB_V + v) * G3 + g];
        }
        Q_s[ts][ss][g] = q;
    }

    if (u == 0) flag[ts] = 0;
    __syncthreads();
    if (u < STATE) { if (hx[(size_t)n * STATE + u] != 0.0f) atomicOr(&flag[ts], 1); }
    if (u < HID) h_s[ts][u] = hx[(size_t)n * STATE + 2 + u];
    __syncthreads();

    float pr0 = hx[(size_t)n * STATE + 72];
    float pr1 = hx[(size_t)n * STATE + 73];
    float pr2 = hx[(size_t)n * STATE + 74];
    float pr3 = hx[(size_t)n * STATE + 75];
    float pr4 = hx[(size_t)n * STATE + 76];
    float pr5 = hx[(size_t)n * STATE + 77];
    if (flag[ts] == 0) pr0 = 1.0f;

    float phib = phi_b[0], critb = critic_b[0];
    float gxl = (half == 0) ? d_gxc[(size_t)n * G3 + g] : 0.f;
    size_t tbase = (size_t)T_STEPS * NB * STATE + (size_t)n * STATE;

    for (int t = 0; t < T_STEPS; t++) {
        // half-matvec: 16 FFMA2 over 4 chains
        unsigned long long acc0 = 0, acc1 = 0, acc2 = 0, acc3 = 0;
        const ulonglong2* h2 = reinterpret_cast<const ulonglong2*>(h_s[ts] + half * 32);
        #pragma unroll
        for (int k = 0; k < 4; k++) {
            ulonglong2 ha = h2[2 * k];
            ulonglong2 hb = h2[2 * k + 1];
            acc0 = fma2(wreg2[4 * k],     ha.x, acc0);
            acc1 = fma2(wreg2[4 * k + 1], ha.y, acc1);
            acc2 = fma2(wreg2[4 * k + 2], hb.x, acc2);
            acc3 = fma2(wreg2[4 * k + 3], hb.y, acc3);
        }
        float2 u0 = unpk(acc0), u1 = unpk(acc1), u2 = unpk(acc2), u3 = unpk(acc3);
        float part = ((u0.x + u0.y) + (u1.x + u1.y))
                   + ((u2.x + u2.y) + (u3.x + u3.y));
        float other = __shfl_xor_sync(0xffffffffu, part, 1);
        if (half == 0) {
            float gx = gxl
                     + pr0 * Q_s[ts][0][g] + pr1 * Q_s[ts][1][g] + pr2 * Q_s[ts][2][g]
                     + pr3 * Q_s[ts][3][g] + pr4 * Q_s[ts][4][g] + pr5 * Q_s[ts][5][g];
            A[ts][g] = gx;
            B[ts][g] = bhh_s[g] + part + other;
            if (t + 1 < T_STEPS)
                gxl = d_gxc[((size_t)(t + 1) * NB + n) * G3 + g];   // prefetch
        }
        BAR_TS();                                               // sync A

        size_t base = ((size_t)t * NB + n) * STATE;
        if (u < HID) {                  // hidden unit u (warps 0,1 of sample)
            float r  = sigf(A[ts][u] + B[ts][u]);
            float z  = sigf(A[ts][u + 64] + B[ts][u + 64]);
            float x  = A[ts][u + 128] + r * B[ts][u + 128];
            float nn = tanhf_fast(x);
            float hn = (1.f - z) * nn + z * h_s[ts][u];
            h_s[ts][u] = hn;
            out[base + 2 + u] = hn;
            if (t == T_STEPS - 1) out[tbase + 2 + u] = hn;
            float pcv = hn * phi_s[u];
            float vcv = hn * crit_s[u];
            #pragma unroll
            for (int m = 16; m > 0; m >>= 1) {
                pcv += __shfl_xor_sync(0xffffffffu, pcv, m);
                vcv += __shfl_xor_sync(0xffffffffu, vcv, m);
            }
            if ((u & 31) == 0) {
                int w = u >> 5;
                red[ts][w] = pcv; red[ts][2 + w] = vcv;
            }
        }
        BAR_TS();                                               // sync B

        // redundant minimal p-update (registers feed next step's gx)
        float c = sigf(red[ts][0] + red[ts][1] + phib);
        float pt = pr5;
        float omc = 1.f - c;
        float pn0 = omc * pr0 + c * (pr0 * pt);
        float pn1 = omc * pr1 + c * (pr0 + pr1 * pt);
        float pn2 = omc * pr2 + c * (pr1 + pr2 * pt);
        float pn3 = omc * pr3 + c * (pr2 + pr3 * pt);
        float pn4 = omc * pr4 + c * (pr3 + pr4 * pt);
        float pn5 = omc * pr5 + c * (pr4 + pr5 * pt);
        if (u == 0) {                    // one thread per sample: scalars + stores
            float v = red[ts][2] + red[ts][3] + critb;
            float inv = __fdividef(1.f, pn0 + pn1 + pn2 + pn3 + pn4 + pn5);
            float act = inputs[((size_t)t * NB + n) * IN_FEAT + ACT_OFF];
            out[base]     = act;
            out[base + 1] = v;
            out[base + 66] = pn0 * inv; out[base + 67] = pn1 * inv;
            out[base + 68] = pn2 * inv; out[base + 69] = pn3 * inv;
            out[base + 70] = pn4 * inv; out[base + 71] = pn5 * inv;
            out[base + 72] = pn0; out[base + 73] = pn1; out[base + 74] = pn2;
            out[base + 75] = pn3; out[base + 76] = pn4; out[base + 77] = pn5;
            if (t == T_STEPS - 1) {
                out[tbase]     = act;
                out[tbase + 1] = v;
                out[tbase + 66] = pn0 * inv; out[tbase + 67] = pn1 * inv;
                out[tbase + 68] = pn2 * inv; out[tbase + 69] = pn3 * inv;
                out[tbase + 70] = pn4 * inv; out[tbase + 71] = pn5 * inv;
                out[tbase + 72] = pn0; out[tbase + 73] = pn1; out[tbase + 74] = pn2;
                out[tbase + 75] = pn3; out[tbase + 76] = pn4; out[tbase + 77] = pn5;
            }
        }
        pr0 = pn0; pr1 = pn1; pr2 = pn2; pr3 = pn3; pr4 = pn4; pr5 = pn5;
    }
}

// ---------------- launcher ---------------------------------------------------
extern "C" void kernel_launch(void* const* d_in, const int* in_sizes, int n_in,
                              void* d_out, int out_size) {
    const float* inputs   = (const float*)d_in[0];
    const float* hx       = (const float*)d_in[1];
    const float* sub_emb  = (const float*)d_in[2];
    const float* obs_emb  = (const float*)d_in[3];
    const float* conv_w   = (const float*)d_in[4];
    const float* conv_b   = (const float*)d_in[5];
    const float* w_ih     = (const float*)d_in[6];
    const float* w_hh     = (const float*)d_in[7];
    const float* b_ih     = (const float*)d_in[8];
    const float* b_hh     = (const float*)d_in[9];
    const float* critic_w = (const float*)d_in[10];
    const float* critic_b = (const float*)d_in[11];
    const float* phi_w    = (const float*)d_in[12];
    const float* phi_b    = (const float*)d_in[13];
    float* out = (float*)d_out;

    k_prep<<<262 * 6, 1024>>>(w_ih);
    k_tabER<<<188, 192>>>(conv_w, obs_emb, sub_emb, conv_b);
    k_tabgx<<<1024, 192>>>(inputs, b_ih);
    k_rec<<<NB / 2, 768>>>(inputs, hx, w_hh, b_hh, critic_w, critic_b, phi_w, phi_b, out);
}

// round 15
// speedup vs baseline: 1.0844x; 1.0844x over previous
#include <cuda_runtime.h>
#include <cuda_fp16.h>
#include <math.h>
#include <stdint.h>

#define T_STEPS 32
#define NB      256
#define HID     64
#define G3      192      // 3*HID
#define SUB_OFF 128
#define ACT_OFF 146
#define IN_FEAT 147
#define STATE   78
#define GRU_IN  8384
#define CONV_COLS 8192
#define SUB_V   20
#define NSUB    6
#define SUBDIM  3

// ---------------- scratch (device globals; no allocations allowed) ----------
__device__ float   d_Wt[GRU_IN * G3];           // full w_ih transposed        6.4 MB
__device__ float   d_R[3 * SUB_V * G3];         // R[(j*20+v)*192+g]
__device__ float   d_Tab[128 * 16 * G3];        // Tab[(pos*16+v)*192+g]       1.6 MB
__device__ __half2 d_Tab2h[64 * 256 * 96];      // Tab2[pp][v1*16+v2][g/2]     6.3 MB
__device__ float   d_gxc[T_STEPS * NB * G3];    // conv-part of gx + b_ih      6.3 MB

// grid barrier state (generation-based; survives graph replays without reset)
__device__ unsigned int          g_cnt = 0;
__device__ volatile unsigned int g_gen = 0;

__device__ __forceinline__ float tanhf_fast(float x) {
    float y;
    asm("tanh.approx.f32 %0, %1;" : "=f"(y) : "f"(x));
    return y;
}
__device__ __forceinline__ float sigf(float x) {       // sigmoid via MUFU.TANH
    return fmaf(0.5f, tanhf_fast(0.5f * x), 0.5f);
}
__device__ __forceinline__ unsigned long long fma2(unsigned long long a,
                                                   unsigned long long b,
                                                   unsigned long long c) {
    unsigned long long d;
    asm("fma.rn.f32x2 %0, %1, %2, %3;" : "=l"(d) : "l"(a), "l"(b), "l"(c));
    return d;
}
__device__ __forceinline__ float2 unpk(unsigned long long v) {
    float2 r;
    asm("mov.b64 {%0,%1}, %2;" : "=f"(r.x), "=f"(r.y) : "l"(v));
    return r;
}

__device__ __forceinline__ void grid_sync(unsigned nb) {
    __syncthreads();
    if (threadIdx.x == 0) {
        unsigned target = g_gen + 1;
        __threadfence();
        unsigned old = atomicAdd(&g_cnt, 1u);
        if (old == nb - 1) {
            g_cnt = 0;
            __threadfence();
            g_gen = target;
        } else {
            while (g_gen < target) { __nanosleep(64); }
        }
        __threadfence();
    }
    __syncthreads();
}

// ---------------- K1: transpose ALL 8384 columns of w_ih --------------------
__global__ void __launch_bounds__(1024) k_prep(const float* __restrict__ w_ih) {
    __shared__ float tile[32][33];
    int cx = blockIdx.x % 262, cy = blockIdx.x / 262;
    int tx = threadIdx.x % 32, ty = threadIdx.x / 32;
    tile[ty][tx] = w_ih[(size_t)(cy * 32 + ty) * GRU_IN + cx * 32 + tx];
    __syncthreads();
    d_Wt[(size_t)(cx * 32 + ty) * G3 + cy * 32 + tx] = tile[tx][ty];
}

// ---------------- K2: Tab (blocks 0..127, E computed in-block) + R (128..187)
__global__ void __launch_bounds__(192) k_tabER(const float* __restrict__ conv_w,
                                               const float* __restrict__ obs_emb,
                                               const float* __restrict__ sub_emb,
                                               const float* __restrict__ conv_b) {
    if (blockIdx.x >= 128) {             // ---- R part ----
        __shared__ float se[64];
        int b = blockIdx.x - 128;        // 0..59
        int j = b / 20, v = b % 20;
        int g = threadIdx.x;
        if (g < 64) se[g] = sub_emb[v * HID + g];
        __syncthreads();
        float acc = 0.f;
        #pragma unroll 8
        for (int h = 0; h < 64; h++)
            acc += d_Wt[(size_t)(CONV_COLS + j * 64 + h) * G3 + g] * se[h];
        d_R[(size_t)(j * SUB_V + v) * G3 + g] = acc;
        return;
    }
    // ---- Tab part ----
    __shared__ float E_s[2048];
    __shared__ float cb_s[128];
    __shared__ float cw[128 * 65];
    __shared__ float oe[16 * 65];
    int pos = blockIdx.x;                // 0..127, pos = d*64 + s
    int d = pos >> 6, s = pos & 63;
    int g = threadIdx.x;

    for (int i = g; i < 128 * 64; i += 192) {
        int o = i >> 6, h = i & 63;
        cw[o * 65 + h] = conv_w[o * 128 + d * 64 + h];
    }
    for (int i = g; i < 1024; i += 192) {
        int v = i >> 6, h = i & 63;
        oe[v * 65 + h] = obs_emb[v * HID + h];
    }
    if (g < 128) cb_s[g] = conv_b[g];
    __syncthreads();

    for (int i = g; i < 2048; i += 192) {
        int o = i >> 4, v = i & 15;
        float a = 0.f;
        #pragma unroll 8
        for (int h = 0; h < 64; h++)
            a += cw[o * 65 + h] * oe[v * 65 + h];
        E_s[i] = a;
    }
    __syncthreads();

    float acc[16];
    #pragma unroll
    for (int v = 0; v < 16; v++) acc[v] = 0.f;
    float cacc = 0.f;
    for (int o = 0; o < 128; o += 8) {
        float w[8];
        #pragma unroll
        for (int k = 0; k < 8; k++)
            w[k] = d_Wt[(size_t)((o + k) * 64 + s) * G3 + g];
        #pragma unroll
        for (int k = 0; k < 8; k++) {
            cacc += w[k] * cb_s[o + k];
            #pragma unroll
            for (int v = 0; v < 16; v++) acc[v] += w[k] * E_s[(o + k) * 16 + v];
        }
    }
    if (d != 0) cacc = 0.f;
    #pragma unroll
    for (int v = 0; v < 16; v++)
        d_Tab[(size_t)(pos * 16 + v) * G3 + g] = acc[v] + cacc;
}

// ---------------- K3: fused tab2h (phase 1) + gxc (phase 2), grid 1024 ------
__global__ void __launch_bounds__(192, 7) k_tabgx(const float* __restrict__ inputs,
                                                  const float* __restrict__ b_ih) {
    {
        int blk = blockIdx.x;            // 0..1023
        int pp = blk >> 4, v1 = blk & 15;
        int lane = threadIdx.x % 48;
        int vg   = threadIdx.x / 48;
        float4 t1 = reinterpret_cast<const float4*>(
            &d_Tab[(size_t)((2 * pp) * 16 + v1) * G3])[lane];
        float4 t2r[4];
        #pragma unroll
        for (int k = 0; k < 4; k++) {
            int v2 = vg * 4 + k;
            t2r[k] = reinterpret_cast<const float4*>(
                &d_Tab[(size_t)((2 * pp + 1) * 16 + v2) * G3])[lane];
        }
        uint2* outb = reinterpret_cast<uint2*>(d_Tab2h + (size_t)(pp * 256 + v1 * 16) * 96);
        #pragma unroll
        for (int k = 0; k < 4; k++) {
            int v2 = vg * 4 + k;
            __half2 h0 = __floats2half2_rn(t1.x + t2r[k].x, t1.y + t2r[k].y);
            __half2 h1 = __floats2half2_rn(t1.z + t2r[k].z, t1.w + t2r[k].w);
            uint2 u;
            u.x = *reinterpret_cast<uint32_t*>(&h0);
            u.y = *reinterpret_cast<uint32_t*>(&h1);
            outb[(size_t)v2 * 48 + lane] = u;
        }
    }

    grid_sync(gridDim.x);

    {
        __shared__ int pv[8][64];
        int base_tn = blockIdx.x * 8;
        for (int i = threadIdx.x; i < 512; i += 192) {
            int s = i >> 6, pp = i & 63;
            const float* row = inputs + (size_t)(base_tn + s) * IN_FEAT;
            pv[s][pp] = __float2int_rn(row[2 * pp]) * 16 + __float2int_rn(row[2 * pp + 1]);
        }
        __syncthreads();
        int s = threadIdx.x / 24;
        int q = threadIdx.x % 24;
        const uint4* tab = reinterpret_cast<const uint4*>(d_Tab2h);
        float4 b0 = reinterpret_cast<const float4*>(b_ih)[q * 2];
        float4 b1 = reinterpret_cast<const float4*>(b_ih)[q * 2 + 1];
        float a0 = b0.x, a1 = b0.y, a2 = b0.z, a3 = b0.w;
        float a4 = b1.x, a5 = b1.y, a6 = b1.z, a7 = b1.w;
        const int* pvr = pv[s];
        #pragma unroll 8
        for (int pp = 0; pp < 64; pp++) {
            uint4 u = tab[(size_t)((pp << 8) + pvr[pp]) * 24 + q];
            const __half2* h = reinterpret_cast<const __half2*>(&u);
            float2 f0 = __half22float2(h[0]);
            float2 f1 = __half22float2(h[1]);
            float2 f2 = __half22float2(h[2]);
            float2 f3 = __half22float2(h[3]);
            a0 += f0.x; a1 += f0.y; a2 += f1.x; a3 += f1.y;
            a4 += f2.x; a5 += f2.y; a6 += f3.x; a7 += f3.y;
        }
        float4* outp = reinterpret_cast<float4*>(d_gxc) + (size_t)(base_tn + s) * 48 + q * 2;
        outp[0] = make_float4(a0, a1, a2, a3);
        outp[1] = make_float4(a4, a5, a6, a7);
    }
}

// ---------------- K4: recurrence, 2 samples/block, split roles --------------
// All 192 threads/sample: w_hh matvec only (no p dependence).
// Threads g<64: also own hidden unit g — gxc loads, activations, heads, p.
#define BAR_TS() asm volatile("bar.sync %0, %1;" :: "r"(ts + 1), "r"(192) : "memory")

__global__ void __launch_bounds__(384) k_rec(
    const float* __restrict__ inputs, const float* __restrict__ hx,
    const float* __restrict__ w_hh, const float* __restrict__ b_hh,
    const float* __restrict__ critic_w, const float* __restrict__ critic_b,
    const float* __restrict__ phi_w, const float* __restrict__ phi_b,
    float* __restrict__ out)
{
    __shared__ float B[2][G3];
    __shared__ __align__(16) float h_s[2][HID];
    __shared__ __align__(16) float Qp[2][G3][8];   // Q transposed+padded, 12 KB
    __shared__ float phi_s[HID], crit_s[HID], bhh_s[G3];
    __shared__ float red[2][4];
    __shared__ int flag[2];

    int ts = threadIdx.x / G3;           // sample slot 0/1
    int g  = threadIdx.x % G3;
    int n  = blockIdx.x * 2 + ts;

    // w row packed as f32x2 pairs (global row is 16B-aligned: g*256 bytes)
    unsigned long long wreg2[32];
    {
        const ulonglong2* wg = reinterpret_cast<const ulonglong2*>(w_hh + (size_t)g * HID);
        #pragma unroll
        for (int k = 0; k < 16; k++) {
            ulonglong2 t = wg[k];
            wreg2[2 * k] = t.x; wreg2[2 * k + 1] = t.y;
        }
    }

    if (ts == 0) {
        bhh_s[g] = b_hh[g];
        if (g < HID) { phi_s[g] = phi_w[g]; crit_s[g] = critic_w[g]; }
    }

    // Qp[row][s]: padded row-major so activation threads use LDS.128
    const float* in0 = inputs + (size_t)n * IN_FEAT;
    #pragma unroll
    for (int s = 0; s < NSUB; s++) {
        float q = 0.f;
        #pragma unroll
        for (int j = 0; j < SUBDIM; j++) {
            int v = __float2int_rn(in0[SUB_OFF + s * SUBDIM + j]);
            q += d_R[(size_t)(j * SUB_V + v) * G3 + g];
        }
        Qp[ts][g][s] = q;
    }

    if (g == 0) flag[ts] = 0;
    __syncthreads();
    if (g < STATE) { if (hx[(size_t)n * STATE + g] != 0.0f) atomicOr(&flag[ts], 1); }
    if (g < HID) h_s[ts][g] = hx[(size_t)n * STATE + 2 + g];
    __syncthreads();

    float pr0 = hx[(size_t)n * STATE + 72];
    float pr1 = hx[(size_t)n * STATE + 73];
    float pr2 = hx[(size_t)n * STATE + 74];
    float pr3 = hx[(size_t)n * STATE + 75];
    float pr4 = hx[(size_t)n * STATE + 76];
    float pr5 = hx[(size_t)n * STATE + 77];
    if (flag[ts] == 0) pr0 = 1.0f;

    float phib = phi_b[0], critb = critic_b[0];
    size_t tbase = (size_t)T_STEPS * NB * STATE + (size_t)n * STATE;

    // activation threads prefetch their 3 gxc values for t=0
    float gr = 0.f, gz = 0.f, gn = 0.f;
    if (g < HID) {
        const float* gx0 = d_gxc + (size_t)n * G3;
        gr = gx0[g]; gz = gx0[g + 64]; gn = gx0[g + 128];
    }

    for (int t = 0; t < T_STEPS; t++) {
        // --- matvec phase (all threads): gh only ---
        unsigned long long acc0 = 0, acc1 = 0, acc2 = 0, acc3 = 0;
        const ulonglong2* h2 = reinterpret_cast<const ulonglong2*>(h_s[ts]);
        #pragma unroll
        for (int k = 0; k < 16; k += 2) {
            ulonglong2 ha = h2[k];
            ulonglong2 hb = h2[k + 1];
            acc0 = fma2(wreg2[2 * k],     ha.x, acc0);
            acc1 = fma2(wreg2[2 * k + 1], ha.y, acc1);
            acc2 = fma2(wreg2[2 * k + 2], hb.x, acc2);
            acc3 = fma2(wreg2[2 * k + 3], hb.y, acc3);
        }
        float2 u0 = unpk(acc0), u1 = unpk(acc1), u2 = unpk(acc2), u3 = unpk(acc3);
        B[ts][g] = bhh_s[g] + ((u0.x + u0.y) + (u1.x + u1.y))
                            + ((u2.x + u2.y) + (u3.x + u3.y));
        BAR_TS();                                               // sync A

        size_t base = ((size_t)t * NB + n) * STATE;
        if (g < HID) {
            // p . Q for the 3 gate rows of unit g (LDS.128 pairs)
            float4 qa0 = *reinterpret_cast<const float4*>(&Qp[ts][g][0]);
            float4 qb0 = *reinterpret_cast<const float4*>(&Qp[ts][g][4]);
            float4 qa1 = *reinterpret_cast<const float4*>(&Qp[ts][g + 64][0]);
            float4 qb1 = *reinterpret_cast<const float4*>(&Qp[ts][g + 64][4]);
            float4 qa2 = *reinterpret_cast<const float4*>(&Qp[ts][g + 128][0]);
            float4 qb2 = *reinterpret_cast<const float4*>(&Qp[ts][g + 128][4]);
            float gx_r = gr + pr0 * qa0.x + pr1 * qa0.y + pr2 * qa0.z
                            + pr3 * qa0.w + pr4 * qb0.x + pr5 * qb0.y;
            float gx_z = gz + pr0 * qa1.x + pr1 * qa1.y + pr2 * qa1.z
                            + pr3 * qa1.w + pr4 * qb1.x + pr5 * qb1.y;
            float gx_n = gn + pr0 * qa2.x + pr1 * qa2.y + pr2 * qa2.z
                            + pr3 * qa2.w + pr4 * qb2.x + pr5 * qb2.y;
            float r  = sigf(gx_r + B[ts][g]);
            float z  = sigf(gx_z + B[ts][g + 64]);
            float x  = gx_n + r * B[ts][g + 128];
            float nn = tanhf_fast(x);
            float hn = (1.f - z) * nn + z * h_s[ts][g];
            h_s[ts][g] = hn;
            out[base + 2 + g] = hn;
            if (t == T_STEPS - 1) out[tbase + 2 + g] = hn;
            if (t + 1 < T_STEPS) {                // prefetch next step's gxc
                const float* gxn = d_gxc + ((size_t)(t + 1) * NB + n) * G3;
                gr = gxn[g]; gz = gxn[g + 64]; gn = gxn[g + 128];
            }
            float pcv = hn * phi_s[g];
            float vcv = hn * crit_s[g];
            #pragma unroll
            for (int m = 16; m > 0; m >>= 1) {
                pcv += __shfl_xor_sync(0xffffffffu, pcv, m);
                vcv += __shfl_xor_sync(0xffffffffu, vcv, m);
            }
            if ((g & 31) == 0) {
                int w = g >> 5;
                red[ts][w] = pcv; red[ts][2 + w] = vcv;
            }
        }
        BAR_TS();                                               // sync B

        if (g < HID) {                   // p-update only in activation warps
            float c = sigf(red[ts][0] + red[ts][1] + phib);
            float pt = pr5;
            float omc = 1.f - c;
            float pn0 = omc * pr0 + c * (pr0 * pt);
            float pn1 = omc * pr1 + c * (pr0 + pr1 * pt);
            float pn2 = omc * pr2 + c * (pr1 + pr2 * pt);
            float pn3 = omc * pr3 + c * (pr2 + pr3 * pt);
            float pn4 = omc * pr4 + c * (pr3 + pr4 * pt);
            float pn5 = omc * pr5 + c * (pr4 + pr5 * pt);
            if (g == 0) {                // one thread: scalars + stores
                float v = red[ts][2] + red[ts][3] + critb;
                float inv = __fdividef(1.f, pn0 + pn1 + pn2 + pn3 + pn4 + pn5);
                float act = inputs[((size_t)t * NB + n) * IN_FEAT + ACT_OFF];
                out[base]     = act;
                out[base + 1] = v;
                out[base + 66] = pn0 * inv; out[base + 67] = pn1 * inv;
                out[base + 68] = pn2 * inv; out[base + 69] = pn3 * inv;
                out[base + 70] = pn4 * inv; out[base + 71] = pn5 * inv;
                out[base + 72] = pn0; out[base + 73] = pn1; out[base + 74] = pn2;
                out[base + 75] = pn3; out[base + 76] = pn4; out[base + 77] = pn5;
                if (t == T_STEPS - 1) {
                    out[tbase]     = act;
                    out[tbase + 1] = v;
                    out[tbase + 66] = pn0 * inv; out[tbase + 67] = pn1 * inv;
                    out[tbase + 68] = pn2 * inv; out[tbase + 69] = pn3 * inv;
                    out[tbase + 70] = pn4 * inv; out[tbase + 71] = pn5 * inv;
                    out[tbase + 72] = pn0; out[tbase + 73] = pn1; out[tbase + 74] = pn2;
                    out[tbase + 75] = pn3; out[tbase + 76] = pn4; out[tbase + 77] = pn5;
                }
            }
            pr0 = pn0; pr1 = pn1; pr2 = pn2; pr3 = pn3; pr4 = pn4; pr5 = pn5;
        }
        // matvec warps proceed directly to the next matvec (h_s ordered by sync B)
    }
}

// ---------------- launcher ---------------------------------------------------
extern "C" void kernel_launch(void* const* d_in, const int* in_sizes, int n_in,
                              void* d_out, int out_size) {
    const float* inputs   = (const float*)d_in[0];
    const float* hx       = (const float*)d_in[1];
    const float* sub_emb  = (const float*)d_in[2];
    const float* obs_emb  = (const float*)d_in[3];
    const float* conv_w   = (const float*)d_in[4];
    const float* conv_b   = (const float*)d_in[5];
    const float* w_ih     = (const float*)d_in[6];
    const float* w_hh     = (const float*)d_in[7];
    const float* b_ih     = (const float*)d_in[8];
    const float* b_hh     = (const float*)d_in[9];
    const float* critic_w = (const float*)d_in[10];
    const float* critic_b = (const float*)d_in[11];
    const float* phi_w    = (const float*)d_in[12];
    const float* phi_b    = (const float*)d_in[13];
    float* out = (float*)d_out;

    k_prep<<<262 * 6, 1024>>>(w_ih);
    k_tabER<<<188, 192>>>(conv_w, obs_emb, sub_emb, conv_b);
    k_tabgx<<<1024, 192>>>(inputs, b_ih);
    k_rec<<<NB / 2, 384>>>(inputs, hx, w_hh, b_hh, critic_w, critic_b, phi_w, phi_b, out);
}

// round 16
// speedup vs baseline: 1.1804x; 1.0885x over previous
#include <cuda_runtime.h>
#include <cuda_fp16.h>
#include <math.h>
#include <stdint.h>

#define T_STEPS 32
#define NB      256
#define HID     64
#define G3      192      // 3*HID
#define SUB_OFF 128
#define ACT_OFF 146
#define IN_FEAT 147
#define STATE   78
#define GRU_IN  8384
#define CONV_COLS 8192
#define SUB_V   20
#define NSUB    6
#define SUBDIM  3

// ---------------- scratch (device globals; no allocations allowed) ----------
__device__ float   d_Wt[GRU_IN * G3];           // full w_ih transposed        6.4 MB
__device__ float   d_R[3 * SUB_V * G3];         // R[(j*20+v)*192+g]
__device__ float   d_Tab[128 * 16 * G3];        // Tab[(pos*16+v)*192+g]       1.6 MB
__device__ __half2 d_Tab2h[64 * 256 * 96];      // Tab2[pp][v1*16+v2][g/2]     6.3 MB
__device__ float   d_gxc[T_STEPS * NB * G3];    // conv-part of gx + b_ih      6.3 MB

// grid barrier state (generation-based; survives graph replays without reset)
__device__ unsigned int          g_cnt = 0;
__device__ volatile unsigned int g_gen = 0;

__device__ __forceinline__ float tanhf_fast(float x) {
    float y;
    asm("tanh.approx.f32 %0, %1;" : "=f"(y) : "f"(x));
    return y;
}
__device__ __forceinline__ float sigf(float x) {       // sigmoid via MUFU.TANH
    return fmaf(0.5f, tanhf_fast(0.5f * x), 0.5f);
}
__device__ __forceinline__ unsigned long long fma2(unsigned long long a,
                                                   unsigned long long b,
                                                   unsigned long long c) {
    unsigned long long d;
    asm("fma.rn.f32x2 %0, %1, %2, %3;" : "=l"(d) : "l"(a), "l"(b), "l"(c));
    return d;
}
__device__ __forceinline__ float2 unpk(unsigned long long v) {
    float2 r;
    asm("mov.b64 {%0,%1}, %2;" : "=f"(r.x), "=f"(r.y) : "l"(v));
    return r;
}

__device__ __forceinline__ void grid_sync(unsigned nb) {
    __syncthreads();
    if (threadIdx.x == 0) {
        unsigned target = g_gen + 1;
        __threadfence();
        unsigned old = atomicAdd(&g_cnt, 1u);
        if (old == nb - 1) {
            g_cnt = 0;
            __threadfence();
            g_gen = target;
        } else {
            while (g_gen < target) { __nanosleep(64); }
        }
        __threadfence();
    }
    __syncthreads();
}

// ---------------- K1: transpose ALL 8384 columns of w_ih --------------------
__global__ void __launch_bounds__(1024) k_prep(const float* __restrict__ w_ih) {
    __shared__ float tile[32][33];
    int cx = blockIdx.x % 262, cy = blockIdx.x / 262;
    int tx = threadIdx.x % 32, ty = threadIdx.x / 32;
    tile[ty][tx] = w_ih[(size_t)(cy * 32 + ty) * GRU_IN + cx * 32 + tx];
    __syncthreads();
    d_Wt[(size_t)(cx * 32 + ty) * G3 + cy * 32 + tx] = tile[tx][ty];
}

// ---------------- K2: Tab (blocks 0..127, E computed in-block) + R (128..187)
__global__ void __launch_bounds__(192) k_tabER(const float* __restrict__ conv_w,
                                               const float* __restrict__ obs_emb,
                                               const float* __restrict__ sub_emb,
                                               const float* __restrict__ conv_b) {
    if (blockIdx.x >= 128) {             // ---- R part ----
        __shared__ float se[64];
        int b = blockIdx.x - 128;        // 0..59
        int j = b / 20, v = b % 20;
        int g = threadIdx.x;
        if (g < 64) se[g] = sub_emb[v * HID + g];
        __syncthreads();
        float acc = 0.f;
        #pragma unroll 8
        for (int h = 0; h < 64; h++)
            acc += d_Wt[(size_t)(CONV_COLS + j * 64 + h) * G3 + g] * se[h];
        d_R[(size_t)(j * SUB_V + v) * G3 + g] = acc;
        return;
    }
    // ---- Tab part ----
    __shared__ float E_s[2048];
    __shared__ float cb_s[128];
    __shared__ float cw[128 * 65];
    __shared__ float oe[16 * 65];
    int pos = blockIdx.x;                // 0..127, pos = d*64 + s
    int d = pos >> 6, s = pos & 63;
    int g = threadIdx.x;

    for (int i = g; i < 128 * 64; i += 192) {
        int o = i >> 6, h = i & 63;
        cw[o * 65 + h] = conv_w[o * 128 + d * 64 + h];
    }
    for (int i = g; i < 1024; i += 192) {
        int v = i >> 6, h = i & 63;
        oe[v * 65 + h] = obs_emb[v * HID + h];
    }
    if (g < 128) cb_s[g] = conv_b[g];
    __syncthreads();

    for (int i = g; i < 2048; i += 192) {
        int o = i >> 4, v = i & 15;
        float a = 0.f;
        #pragma unroll 8
        for (int h = 0; h < 64; h++)
            a += cw[o * 65 + h] * oe[v * 65 + h];
        E_s[i] = a;
    }
    __syncthreads();

    float acc[16];
    #pragma unroll
    for (int v = 0; v < 16; v++) acc[v] = 0.f;
    float cacc = 0.f;
    for (int o = 0; o < 128; o += 8) {
        float w[8];
        #pragma unroll
        for (int k = 0; k < 8; k++)
            w[k] = d_Wt[(size_t)((o + k) * 64 + s) * G3 + g];
        #pragma unroll
        for (int k = 0; k < 8; k++) {
            cacc += w[k] * cb_s[o + k];
            #pragma unroll
            for (int v = 0; v < 16; v++) acc[v] += w[k] * E_s[(o + k) * 16 + v];
        }
    }
    if (d != 0) cacc = 0.f;
    #pragma unroll
    for (int v = 0; v < 16; v++)
        d_Tab[(size_t)(pos * 16 + v) * G3 + g] = acc[v] + cacc;
}

// ---------------- K3: fused tab2h (phase 1) + gxc (phase 2), grid 1024 ------
__global__ void __launch_bounds__(192, 7) k_tabgx(const float* __restrict__ inputs,
                                                  const float* __restrict__ b_ih) {
    {
        int blk = blockIdx.x;            // 0..1023
        int pp = blk >> 4, v1 = blk & 15;
        int lane = threadIdx.x % 48;
        int vg   = threadIdx.x / 48;
        float4 t1 = reinterpret_cast<const float4*>(
            &d_Tab[(size_t)((2 * pp) * 16 + v1) * G3])[lane];
        float4 t2r[4];
        #pragma unroll
        for (int k = 0; k < 4; k++) {
            int v2 = vg * 4 + k;
            t2r[k] = reinterpret_cast<const float4*>(
                &d_Tab[(size_t)((2 * pp + 1) * 16 + v2) * G3])[lane];
        }
        uint2* outb = reinterpret_cast<uint2*>(d_Tab2h + (size_t)(pp * 256 + v1 * 16) * 96);
        #pragma unroll
        for (int k = 0; k < 4; k++) {
            int v2 = vg * 4 + k;
            __half2 h0 = __floats2half2_rn(t1.x + t2r[k].x, t1.y + t2r[k].y);
            __half2 h1 = __floats2half2_rn(t1.z + t2r[k].z, t1.w + t2r[k].w);
            uint2 u;
            u.x = *reinterpret_cast<uint32_t*>(&h0);
            u.y = *reinterpret_cast<uint32_t*>(&h1);
            outb[(size_t)v2 * 48 + lane] = u;
        }
    }

    grid_sync(gridDim.x);

    {
        __shared__ int pv[8][64];
        int base_tn = blockIdx.x * 8;
        for (int i = threadIdx.x; i < 512; i += 192) {
            int s = i >> 6, pp = i & 63;
            const float* row = inputs + (size_t)(base_tn + s) * IN_FEAT;
            pv[s][pp] = __float2int_rn(row[2 * pp]) * 16 + __float2int_rn(row[2 * pp + 1]);
        }
        __syncthreads();
        int s = threadIdx.x / 24;
        int q = threadIdx.x % 24;
        const uint4* tab = reinterpret_cast<const uint4*>(d_Tab2h);
        float4 b0 = reinterpret_cast<const float4*>(b_ih)[q * 2];
        float4 b1 = reinterpret_cast<const float4*>(b_ih)[q * 2 + 1];
        float a0 = b0.x, a1 = b0.y, a2 = b0.z, a3 = b0.w;
        float a4 = b1.x, a5 = b1.y, a6 = b1.z, a7 = b1.w;
        const int* pvr = pv[s];
        #pragma unroll 8
        for (int pp = 0; pp < 64; pp++) {
            uint4 u = tab[(size_t)((pp << 8) + pvr[pp]) * 24 + q];
            const __half2* h = reinterpret_cast<const __half2*>(&u);
            float2 f0 = __half22float2(h[0]);
            float2 f1 = __half22float2(h[1]);
            float2 f2 = __half22float2(h[2]);
            float2 f3 = __half22float2(h[3]);
            a0 += f0.x; a1 += f0.y; a2 += f1.x; a3 += f1.y;
            a4 += f2.x; a5 += f2.y; a6 += f3.x; a7 += f3.y;
        }
        float4* outp = reinterpret_cast<float4*>(d_gxc) + (size_t)(base_tn + s) * 48 + q * 2;
        outp[0] = make_float4(a0, a1, a2, a3);
        outp[1] = make_float4(a4, a5, a6, a7);
    }
}

// ---------------- K4: recurrence — producer/consumer warp specialization ----
// 2 samples/block, 256 threads/sample: u<192 = matvec rows (w in regs),
// u>=192 = activation units (q/p/h_prev in regs). Named-barrier split lets
// the next matvec overlap the head-reduction + p-update.
#define BSYNC(id)  asm volatile("bar.sync %0, %1;"   :: "r"(id), "r"(256) : "memory")
#define BARRV(id)  asm volatile("bar.arrive %0, %1;" :: "r"(id), "r"(256) : "memory")
#define BSYNC64(id) asm volatile("bar.sync %0, %1;"  :: "r"(id), "r"(64)  : "memory")

__global__ void __launch_bounds__(512) k_rec(
    const float* __restrict__ inputs, const float* __restrict__ hx,
    const float* __restrict__ w_hh, const float* __restrict__ b_hh,
    const float* __restrict__ critic_w, const float* __restrict__ critic_b,
    const float* __restrict__ phi_w, const float* __restrict__ phi_b,
    float* __restrict__ out)
{
    __shared__ float B[2][G3];
    __shared__ __align__(16) float h_s[2][HID];
    __shared__ float red[2][4];
    __shared__ int flag[2];

    int ts = threadIdx.x >> 8;           // sample slot 0/1
    int u  = threadIdx.x & 255;
    int n  = blockIdx.x * 2 + ts;
    int barA = 1 + ts, barB = 3 + ts, barC = 5 + ts;

    if (u == 0) flag[ts] = 0;
    __syncthreads();
    if (u < STATE) { if (hx[(size_t)n * STATE + u] != 0.0f) atomicOr(&flag[ts], 1); }
    if (u < HID) h_s[ts][u] = hx[(size_t)n * STATE + 2 + u];
    __syncthreads();

    size_t tbase = (size_t)T_STEPS * NB * STATE + (size_t)n * STATE;

    if (u < G3) {
        // ================= matvec group: row g = u =================
        int g = u;
        unsigned long long wreg2[32];
        {
            const ulonglong2* wg = reinterpret_cast<const ulonglong2*>(w_hh + (size_t)g * HID);
            #pragma unroll
            for (int k = 0; k < 16; k++) {
                ulonglong2 t = wg[k];
                wreg2[2 * k] = t.x; wreg2[2 * k + 1] = t.y;
            }
        }
        float bhh = b_hh[g];
        for (int t = 0; t < T_STEPS; t++) {
            if (t) BSYNC(barB);          // wait for h(t)
            unsigned long long acc0 = 0, acc1 = 0, acc2 = 0, acc3 = 0;
            const ulonglong2* h2 = reinterpret_cast<const ulonglong2*>(h_s[ts]);
            #pragma unroll
            for (int k = 0; k < 16; k += 2) {
                ulonglong2 ha = h2[k];
                ulonglong2 hb = h2[k + 1];
                acc0 = fma2(wreg2[2 * k],     ha.x, acc0);
                acc1 = fma2(wreg2[2 * k + 1], ha.y, acc1);
                acc2 = fma2(wreg2[2 * k + 2], hb.x, acc2);
                acc3 = fma2(wreg2[2 * k + 3], hb.y, acc3);
            }
            float2 u0 = unpk(acc0), u1 = unpk(acc1), u2 = unpk(acc2), u3 = unpk(acc3);
            B[ts][g] = bhh + ((u0.x + u0.y) + (u1.x + u1.y))
                           + ((u2.x + u2.y) + (u3.x + u3.y));
            BARRV(barA);                 // B(t) ready
        }
    } else {
        // ================= activation group: unit e ==================
        int e = u - G3;                  // 0..63
        float phi_e = phi_w[e], crit_e = critic_w[e];
        float phib = phi_b[0], critb = critic_b[0];

        // loop-invariant Q in registers: q[row 0..2][s 0..5]
        float q[3][6];
        const float* in0 = inputs + (size_t)n * IN_FEAT;
        #pragma unroll
        for (int s = 0; s < NSUB; s++) {
            int v0 = __float2int_rn(in0[SUB_OFF + s * SUBDIM + 0]);
            int v1 = __float2int_rn(in0[SUB_OFF + s * SUBDIM + 1]);
            int v2 = __float2int_rn(in0[SUB_OFF + s * SUBDIM + 2]);
            #pragma unroll
            for (int rr = 0; rr < 3; rr++) {
                int row = e + rr * 64;
                q[rr][s] = d_R[(size_t)(0 * SUB_V + v0) * G3 + row]
                         + d_R[(size_t)(1 * SUB_V + v1) * G3 + row]
                         + d_R[(size_t)(2 * SUB_V + v2) * G3 + row];
            }
        }

        float pr0 = hx[(size_t)n * STATE + 72];
        float pr1 = hx[(size_t)n * STATE + 73];
        float pr2 = hx[(size_t)n * STATE + 74];
        float pr3 = hx[(size_t)n * STATE + 75];
        float pr4 = hx[(size_t)n * STATE + 76];
        float pr5 = hx[(size_t)n * STATE + 77];
        if (flag[ts] == 0) pr0 = 1.0f;

        float h_prev = h_s[ts][e];
        const float* gx0 = d_gxc + (size_t)n * G3;
        float gr = gx0[e], gz = gx0[e + 64], gn = gx0[e + 128];

        for (int t = 0; t < T_STEPS; t++) {
            BSYNC(barA);                 // wait for B(t)
            float Br = B[ts][e], Bz = B[ts][e + 64], Bn = B[ts][e + 128];
            float gx_r = gr + pr0 * q[0][0] + pr1 * q[0][1] + pr2 * q[0][2]
                            + pr3 * q[0][3] + pr4 * q[0][4] + pr5 * q[0][5];
            float gx_z = gz + pr0 * q[1][0] + pr1 * q[1][1] + pr2 * q[1][2]
                            + pr3 * q[1][3] + pr4 * q[1][4] + pr5 * q[1][5];
            float gx_n = gn + pr0 * q[2][0] + pr1 * q[2][1] + pr2 * q[2][2]
                            + pr3 * q[2][3] + pr4 * q[2][4] + pr5 * q[2][5];
            float r  = sigf(gx_r + Br);
            float z  = sigf(gx_z + Bz);
            float x  = gx_n + r * Bn;
            float nn = tanhf_fast(x);
            float hn = (1.f - z) * nn + z * h_prev;
            h_s[ts][e] = hn;             // STS before barC/arrive -> visible to matvec
            h_prev = hn;

            // head partials (independent of matvec)
            float pcv = hn * phi_e;
            float vcv = hn * crit_e;
            #pragma unroll
            for (int m = 16; m > 0; m >>= 1) {
                pcv += __shfl_xor_sync(0xffffffffu, pcv, m);
                vcv += __shfl_xor_sync(0xffffffffu, vcv, m);
            }
            if ((e & 31) == 0) {
                int w = e >> 5;
                red[ts][w] = pcv; red[ts][2 + w] = vcv;
            }
            BSYNC64(barC);               // h + red ordered among the 2 A-warps
            if (t + 1 < T_STEPS) BARRV(barB);   // release matvec for t+1

            // ---- overlapped with next matvec: scalars, p-update, stores ----
            if (t + 1 < T_STEPS) {       // prefetch next gxc
                const float* gxn = d_gxc + ((size_t)(t + 1) * NB + n) * G3;
                gr = gxn[e]; gz = gxn[e + 64]; gn = gxn[e + 128];
            }
            float c = sigf(red[ts][0] + red[ts][1] + phib);
            float pt = pr5;
            float omc = 1.f - c;
            float pn0 = omc * pr0 + c * (pr0 * pt);
            float pn1 = omc * pr1 + c * (pr0 + pr1 * pt);
            float pn2 = omc * pr2 + c * (pr1 + pr2 * pt);
            float pn3 = omc * pr3 + c * (pr2 + pr3 * pt);
            float pn4 = omc * pr4 + c * (pr3 + pr4 * pt);
            float pn5 = omc * pr5 + c * (pr4 + pr5 * pt);
            size_t base = ((size_t)t * NB + n) * STATE;
            out[base + 2 + e] = hn;
            if (t == T_STEPS - 1) out[tbase + 2 + e] = hn;
            if (e == 0) {
                float v = red[ts][2] + red[ts][3] + critb;
                float inv = __fdividef(1.f, pn0 + pn1 + pn2 + pn3 + pn4 + pn5);
                float act = inputs[((size_t)t * NB + n) * IN_FEAT + ACT_OFF];
                out[base]     = act;
                out[base + 1] = v;
                out[base + 66] = pn0 * inv; out[base + 67] = pn1 * inv;
                out[base + 68] = pn2 * inv; out[base + 69] = pn3 * inv;
                out[base + 70] = pn4 * inv; out[base + 71] = pn5 * inv;
                out[base + 72] = pn0; out[base + 73] = pn1; out[base + 74] = pn2;
                out[base + 75] = pn3; out[base + 76] = pn4; out[base + 77] = pn5;
                if (t == T_STEPS - 1) {
                    out[tbase]     = act;
                    out[tbase + 1] = v;
                    out[tbase + 66] = pn0 * inv; out[tbase + 67] = pn1 * inv;
                    out[tbase + 68] = pn2 * inv; out[tbase + 69] = pn3 * inv;
                    out[tbase + 70] = pn4 * inv; out[tbase + 71] = pn5 * inv;
                    out[tbase + 72] = pn0; out[tbase + 73] = pn1; out[tbase + 74] = pn2;
                    out[tbase + 75] = pn3; out[tbase + 76] = pn4; out[tbase + 77] = pn5;
                }
            }
            pr0 = pn0; pr1 = pn1; pr2 = pn2; pr3 = pn3; pr4 = pn4; pr5 = pn5;
        }
    }
}

// ---------------- launcher ---------------------------------------------------
extern "C" void kernel_launch(void* const* d_in, const int* in_sizes, int n_in,
                              void* d_out, int out_size) {
    const float* inputs   = (const float*)d_in[0];
    const float* hx       = (const float*)d_in[1];
    const float* sub_emb  = (const float*)d_in[2];
    const float* obs_emb  = (const float*)d_in[3];
    const float* conv_w   = (const float*)d_in[4];
    const float* conv_b   = (const float*)d_in[5];
    const float* w_ih     = (const float*)d_in[6];
    const float* w_hh     = (const float*)d_in[7];
    const float* b_ih     = (const float*)d_in[8];
    const float* b_hh     = (const float*)d_in[9];
    const float* critic_w = (const float*)d_in[10];
    const float* critic_b = (const float*)d_in[11];
    const float* phi_w    = (const float*)d_in[12];
    const float* phi_b    = (const float*)d_in[13];
    float* out = (float*)d_out;

    k_prep<<<262 * 6, 1024>>>(w_ih);
    k_tabER<<<188, 192>>>(conv_w, obs_emb, sub_emb, conv_b);
    k_tabgx<<<1024, 192>>>(inputs, b_ih);
    k_rec<<<NB / 2, 512>>>(inputs, hx, w_hh, b_hh, critic_w, critic_b, phi_w, phi_b, out);
}